// round 14
// baseline (speedup 1.0000x reference)
#include <cuda_runtime.h>
#include <cstdint>

// out[b,n,m] = sum_d x1[b,n,d]*x2[b,m,d] + const   (B=4, N=M=4096, D=32, fp32)
//
// Round 13: R12 (best: 73.7us) + LDS.128 fragment packing.
//  k-relabel: gmem quad q staged at 16B-unit (2*(q&3)+(q>>2)) ^ (row&7).
//  Thread t4's frags for mma steps {2h,2h+1} occupy ONE 16B unit
//  (2t4+h)^(r&7): mainloop does 16 LDS.128 instead of 32 LDS.64 per thread.
//  Conflict-free both directions (staging: units 0..7 per row-phase;
//  mainloop: bit0=h^g0, bits1-2=t4^(g>>1) -> 8 distinct units per phase).
//  Everything else identical to R12: cp.async staging, tf32-by-truncation,
//  bperm'd B rows -> contiguous STG.128 epilogue with __stcs, 8192 CTAs,
//  256 thr, 4 CTAs/SM.

#define TILE_M 128
#define TILE_N 64
#define DDIM 32
#define A_WORDS (TILE_M * 32)       // 4096 words, 16KB
#define B_WORDS (TILE_N * 32)       // 2048 words, 8KB

__device__ __forceinline__ uint32_t smem_to_u32(const void* p) {
    uint32_t a;
    asm("{ .reg .u64 t; cvta.to.shared.u64 t, %1; cvt.u32.u64 %0, t; }" : "=r"(a) : "l"(p));
    return a;
}

__device__ __forceinline__ void cp_async16(uint32_t smem_dst, const void* gsrc) {
    asm volatile("cp.async.cg.shared.global [%0], [%1], 16;"
                 :: "r"(smem_dst), "l"(gsrc) : "memory");
}

__device__ __forceinline__ void mma_tf32_16x8x8(
    float& d0, float& d1, float& d2, float& d3,
    uint32_t a0, uint32_t a1, uint32_t a2, uint32_t a3,
    uint32_t b0, uint32_t b1) {
    asm volatile(
        "mma.sync.aligned.m16n8k8.row.col.f32.tf32.tf32.f32 "
        "{%0,%1,%2,%3}, {%4,%5,%6,%7}, {%8,%9}, {%0,%1,%2,%3};"
        : "+f"(d0), "+f"(d1), "+f"(d2), "+f"(d3)
        : "r"(a0), "r"(a1), "r"(a2), "r"(a3), "r"(b0), "r"(b1));
}

// B row permutation (involution): within each 32-block, r = 8b+2a+e -> 8a+2b+e.
// Makes mma frag col (8nt+2t4+e) correspond to gmem col (8t4+2nt+e):
// each thread's 8 values per output row are contiguous -> STG.128 epilogue.
__device__ __forceinline__ int bperm(int r) {
    int blk = r & ~31;
    int u = r & 31;
    int a = u >> 3, bb = (u & 7) >> 1, e = u & 1;
    return blk + (bb << 3) + (a << 1) + e;
}

// Staging unit for gmem quad q in (slot-)row r: contains k-slots for
// thread t4=q&3, mma steps 2*(q>>2), 2*(q>>2)+1.
__device__ __forceinline__ int stage_unit(int q, int r) {
    return (2 * (q & 3) + (q >> 2)) ^ (r & 7);
}

__global__ __launch_bounds__(256, 4)
void bmm_mma_kernel(const float* __restrict__ x1,
                    const float* __restrict__ x2,
                    const float* __restrict__ cptr,
                    float* __restrict__ out) {
    __shared__ uint32_t As[A_WORDS];
    __shared__ uint32_t Bs[B_WORDS];

    const int tid = threadIdx.x;
    const int wid = tid >> 5;
    const int lid = tid & 31;
    const int g   = lid >> 2;     // groupID 0..7
    const int t4  = lid & 3;      // thread-in-group 0..3
    const int warp_m = wid & 3;   // 0..3  (32-row block)
    const int warp_n = wid >> 2;  // 0..1  (32-col block)
    const int b = blockIdx.z;
    const int N = 4096, M = 4096;

    // ---- Stage A: cp.async 16B into packed-unit layout ----
    const float* a_base = x1 + ((size_t)b * N + (size_t)blockIdx.y * TILE_M) * DDIM;
    const uint32_t aS = smem_to_u32(As);
    #pragma unroll
    for (int i = 0; i < 4; i++) {
        int s = tid + i * 256;        // 0..1023
        int row = s >> 3;
        int q   = s & 7;
        cp_async16(aS + (row * 32 + 4 * stage_unit(q, row)) * 4,
                   a_base + (size_t)row * DDIM + q * 4);
    }
    // ---- Stage B: bperm'd row slot, unit keyed on slot ----
    const float* b_base = x2 + ((size_t)b * M + (size_t)blockIdx.x * TILE_N) * DDIM;
    const uint32_t bS = smem_to_u32(Bs);
    #pragma unroll
    for (int i = 0; i < 2; i++) {
        int s = tid + i * 256;        // 0..511
        int row = s >> 3;
        int q   = s & 7;
        int slot = bperm(row);
        cp_async16(bS + (slot * 32 + 4 * stage_unit(q, slot)) * 4,
                   b_base + (size_t)row * DDIM + q * 4);
    }
    asm volatile("cp.async.commit_group;" ::: "memory");
    const float cbias = cptr[0];
    asm volatile("cp.async.wait_group 0;" ::: "memory");
    __syncthreads();

    // ---- MMA mainloop: warp tile 32x32, 2 jhalves x 2 j-steps of k=8 ----
    float acc[2][4][4];
    #pragma unroll
    for (int mt = 0; mt < 2; mt++)
        #pragma unroll
        for (int nt = 0; nt < 4; nt++)
            #pragma unroll
            for (int r = 0; r < 4; r++)
                acc[mt][nt][r] = 0.0f;

    const int arow0 = warp_m * 32 + g;
    const int brow0 = warp_n * 32 + g;
    #pragma unroll
    for (int h = 0; h < 2; h++) {
        // unit (2t4+h) ^ (r&7); r&7 == g for all our rows (offsets are mult of 8)
        const int uoff = 4 * ((2 * t4 + h) ^ g);
        // A: rows g, g+8 per mt
        uint4 va[2][2];
        #pragma unroll
        for (int mt = 0; mt < 2; mt++) {
            int r0 = arow0 + mt * 16;
            va[mt][0] = *(const uint4*)&As[r0 * 32 + uoff];
            va[mt][1] = *(const uint4*)&As[(r0 + 8) * 32 + uoff];
        }
        uint4 vb[4];
        #pragma unroll
        for (int nt = 0; nt < 4; nt++)
            vb[nt] = *(const uint4*)&Bs[(brow0 + nt * 8) * 32 + uoff];

        #pragma unroll
        for (int mt = 0; mt < 2; mt++)
            #pragma unroll
            for (int nt = 0; nt < 4; nt++) {
                // j = 2h   : words .x (e0), .y (e1)
                mma_tf32_16x8x8(acc[mt][nt][0], acc[mt][nt][1],
                                acc[mt][nt][2], acc[mt][nt][3],
                                va[mt][0].x, va[mt][1].x,
                                va[mt][0].y, va[mt][1].y,
                                vb[nt].x, vb[nt].y);
                // j = 2h+1 : words .z (e0), .w (e1)
                mma_tf32_16x8x8(acc[mt][nt][0], acc[mt][nt][1],
                                acc[mt][nt][2], acc[mt][nt][3],
                                va[mt][0].z, va[mt][1].z,
                                va[mt][0].w, va[mt][1].w,
                                vb[nt].z, vb[nt].w);
            }
    }

    // ---- Epilogue: contiguous streaming stores (evict-first) ----
    const size_t row_base = (size_t)b * N + (size_t)blockIdx.y * TILE_M + warp_m * 32;
    const size_t col0 = (size_t)blockIdx.x * TILE_N + warp_n * 32 + 8 * t4;
    #pragma unroll
    for (int mt = 0; mt < 2; mt++) {
        size_t r0 = row_base + mt * 16 + g;
        float* p0 = out + r0 * M + col0;         // row g
        float* p1 = out + (r0 + 8) * M + col0;   // row g+8
        float4 v;
        v = make_float4(acc[mt][0][0] + cbias, acc[mt][0][1] + cbias,
                        acc[mt][1][0] + cbias, acc[mt][1][1] + cbias);
        __stcs((float4*)(p0), v);
        v = make_float4(acc[mt][2][0] + cbias, acc[mt][2][1] + cbias,
                        acc[mt][3][0] + cbias, acc[mt][3][1] + cbias);
        __stcs((float4*)(p0 + 4), v);
        v = make_float4(acc[mt][0][2] + cbias, acc[mt][0][3] + cbias,
                        acc[mt][1][2] + cbias, acc[mt][1][3] + cbias);
        __stcs((float4*)(p1), v);
        v = make_float4(acc[mt][2][2] + cbias, acc[mt][2][3] + cbias,
                        acc[mt][3][2] + cbias, acc[mt][3][3] + cbias);
        __stcs((float4*)(p1 + 4), v);
    }
}

extern "C" void kernel_launch(void* const* d_in, const int* in_sizes, int n_in,
                              void* d_out, int out_size) {
    const float* x1  = (const float*)d_in[0];   // [4, 4096, 32]
    const float* x2  = (const float*)d_in[1];   // [4, 4096, 32]
    const float* cst = (const float*)d_in[2];   // [1]
    float* out       = (float*)d_out;           // [4, 4096, 4096]

    dim3 grid(4096 / TILE_N, 4096 / TILE_M, 4);   // 64 x 32 x 4 = 8192
    bmm_mma_kernel<<<grid, 256>>>(x1, x2, cst, out);
}

// round 15
// speedup vs baseline: 1.5840x; 1.5840x over previous
#include <cuda_runtime.h>
#include <cstdint>

// out[b,n,m] = sum_d x1[b,n,d]*x2[b,m,d] + const   (B=4, N=M=4096, D=32, fp32)
//
// Round 14: revert to R12 exactly (proven best: 73.7us).
// R13's LDS.128 packing regressed 1.6x -- evidence points to 2-way LDS bank
// conflicts under t4-aligned quarter-warp phase grouping for 128-bit shared
// loads. LDS.64 + XOR swizzle is the verified conflict-free floor.
//  - staging: cp.async (LDGSTS.128) gmem->smem, XOR swizzle q^(2*(row&3))
//  - tf32 via register truncation inside mma (no cvt)
//  - mainloop: warp tile 32x32, conflict-free LDS.64
//  - epilogue: bperm'd B rows -> contiguous STG.128 with __stcs (evict-first)
//  - 8192 CTAs, 256 thr, 4 CTAs/SM (reg-capped at 64).

#define TILE_M 128
#define TILE_N 64
#define DDIM 32
#define A_WORDS (TILE_M * 32)       // 4096 words, 16KB
#define B_WORDS (TILE_N * 32)       // 2048 words, 8KB

__device__ __forceinline__ uint32_t smem_to_u32(const void* p) {
    uint32_t a;
    asm("{ .reg .u64 t; cvta.to.shared.u64 t, %1; cvt.u32.u64 %0, t; }" : "=r"(a) : "l"(p));
    return a;
}

__device__ __forceinline__ void cp_async16(uint32_t smem_dst, const void* gsrc) {
    asm volatile("cp.async.cg.shared.global [%0], [%1], 16;"
                 :: "r"(smem_dst), "l"(gsrc) : "memory");
}

__device__ __forceinline__ void mma_tf32_16x8x8(
    float& d0, float& d1, float& d2, float& d3,
    uint32_t a0, uint32_t a1, uint32_t a2, uint32_t a3,
    uint32_t b0, uint32_t b1) {
    asm volatile(
        "mma.sync.aligned.m16n8k8.row.col.f32.tf32.tf32.f32 "
        "{%0,%1,%2,%3}, {%4,%5,%6,%7}, {%8,%9}, {%0,%1,%2,%3};"
        : "+f"(d0), "+f"(d1), "+f"(d2), "+f"(d3)
        : "r"(a0), "r"(a1), "r"(a2), "r"(a3), "r"(b0), "r"(b1));
}

// B row permutation (involution): within each 32-block, r = 8b+2a+e -> 8a+2b+e.
// Makes mma frag col (8nt+2t4+e) correspond to gmem col (8t4+2nt+e):
// each thread's 8 values per output row are contiguous -> STG.128 epilogue.
__device__ __forceinline__ int bperm(int r) {
    int blk = r & ~31;
    int u = r & 31;
    int a = u >> 3, bb = (u & 7) >> 1, e = u & 1;
    return blk + (bb << 3) + (a << 1) + e;
}

__global__ __launch_bounds__(256, 4)
void bmm_mma_kernel(const float* __restrict__ x1,
                    const float* __restrict__ x2,
                    const float* __restrict__ cptr,
                    float* __restrict__ out) {
    __shared__ uint32_t As[A_WORDS];
    __shared__ uint32_t Bs[B_WORDS];

    const int tid = threadIdx.x;
    const int wid = tid >> 5;
    const int lid = tid & 31;
    const int g   = lid >> 2;     // groupID 0..7
    const int t4  = lid & 3;      // thread-in-group 0..3
    const int warp_m = wid & 3;   // 0..3  (32-row block)
    const int warp_n = wid >> 2;  // 0..1  (32-col block)
    const int b = blockIdx.z;
    const int N = 4096, M = 4096;

    // ---- Stage A: cp.async 16B, swizzled dst (q' = q ^ 2*(row&3)) ----
    const float* a_base = x1 + ((size_t)b * N + (size_t)blockIdx.y * TILE_M) * DDIM;
    const uint32_t aS = smem_to_u32(As);
    #pragma unroll
    for (int i = 0; i < 4; i++) {
        int s = tid + i * 256;        // 0..1023
        int row = s >> 3;
        int q   = s & 7;
        int qp = q ^ (2 * (row & 3));
        cp_async16(aS + (row * 32 + 4 * qp) * 4,
                   a_base + (size_t)row * DDIM + q * 4);
    }
    // ---- Stage B: permuted row slot, same swizzle keyed on slot ----
    const float* b_base = x2 + ((size_t)b * M + (size_t)blockIdx.x * TILE_N) * DDIM;
    const uint32_t bS = smem_to_u32(Bs);
    #pragma unroll
    for (int i = 0; i < 2; i++) {
        int s = tid + i * 256;        // 0..511
        int row = s >> 3;
        int q   = s & 7;
        int slot = bperm(row);
        int qp = q ^ (2 * (slot & 3));
        cp_async16(bS + (slot * 32 + 4 * qp) * 4,
                   b_base + (size_t)row * DDIM + q * 4);
    }
    asm volatile("cp.async.commit_group;" ::: "memory");
    const float cbias = cptr[0];
    asm volatile("cp.async.wait_group 0;" ::: "memory");
    __syncthreads();

    // ---- MMA mainloop: warp tile 32x32, 4 k-steps of 8 ----
    float acc[2][4][4];
    #pragma unroll
    for (int mt = 0; mt < 2; mt++)
        #pragma unroll
        for (int nt = 0; nt < 4; nt++)
            #pragma unroll
            for (int r = 0; r < 4; r++)
                acc[mt][nt][r] = 0.0f;

    const int gx = g & 3;
    const int arow0 = warp_m * 32 + g;
    const int brow0 = warp_n * 32 + g;
    #pragma unroll
    for (int j = 0; j < 4; j++) {
        const int coff = 8 * (j ^ gx) + 2 * t4;   // swizzled k-pair column
        uint2 apair[2][2];
        #pragma unroll
        for (int mt = 0; mt < 2; mt++) {
            int r0 = arow0 + mt * 16;
            apair[mt][0] = *(const uint2*)&As[r0 * 32 + coff];
            apair[mt][1] = *(const uint2*)&As[(r0 + 8) * 32 + coff];
        }
        uint2 bpair[4];
        #pragma unroll
        for (int nt = 0; nt < 4; nt++)
            bpair[nt] = *(const uint2*)&Bs[(brow0 + nt * 8) * 32 + coff];

        #pragma unroll
        for (int mt = 0; mt < 2; mt++)
            #pragma unroll
            for (int nt = 0; nt < 4; nt++)
                mma_tf32_16x8x8(acc[mt][nt][0], acc[mt][nt][1],
                                acc[mt][nt][2], acc[mt][nt][3],
                                apair[mt][0].x, apair[mt][1].x,
                                apair[mt][0].y, apair[mt][1].y,
                                bpair[nt].x, bpair[nt].y);
    }

    // ---- Epilogue: contiguous streaming stores (evict-first) ----
    const size_t row_base = (size_t)b * N + (size_t)blockIdx.y * TILE_M + warp_m * 32;
    const size_t col0 = (size_t)blockIdx.x * TILE_N + warp_n * 32 + 8 * t4;
    #pragma unroll
    for (int mt = 0; mt < 2; mt++) {
        size_t r0 = row_base + mt * 16 + g;
        float* p0 = out + r0 * M + col0;         // row g
        float* p1 = out + (r0 + 8) * M + col0;   // row g+8
        float4 v;
        v = make_float4(acc[mt][0][0] + cbias, acc[mt][0][1] + cbias,
                        acc[mt][1][0] + cbias, acc[mt][1][1] + cbias);
        __stcs((float4*)(p0), v);
        v = make_float4(acc[mt][2][0] + cbias, acc[mt][2][1] + cbias,
                        acc[mt][3][0] + cbias, acc[mt][3][1] + cbias);
        __stcs((float4*)(p0 + 4), v);
        v = make_float4(acc[mt][0][2] + cbias, acc[mt][0][3] + cbias,
                        acc[mt][1][2] + cbias, acc[mt][1][3] + cbias);
        __stcs((float4*)(p1), v);
        v = make_float4(acc[mt][2][2] + cbias, acc[mt][2][3] + cbias,
                        acc[mt][3][2] + cbias, acc[mt][3][3] + cbias);
        __stcs((float4*)(p1 + 4), v);
    }
}

extern "C" void kernel_launch(void* const* d_in, const int* in_sizes, int n_in,
                              void* d_out, int out_size) {
    const float* x1  = (const float*)d_in[0];   // [4, 4096, 32]
    const float* x2  = (const float*)d_in[1];   // [4, 4096, 32]
    const float* cst = (const float*)d_in[2];   // [1]
    float* out       = (float*)d_out;           // [4, 4096, 4096]

    dim3 grid(4096 / TILE_N, 4096 / TILE_M, 4);   // 64 x 32 x 4 = 8192
    bmm_mma_kernel<<<grid, 256>>>(x1, x2, cst, out);
}